// round 5
// baseline (speedup 1.0000x reference)
#include <cuda_runtime.h>
#include <cuda_bf16.h>

// Problem shape (fixed by reference setup_inputs)
#define NB 64
#define LL 512
#define DD 840
#define NVEC (DD / 4)   // 210 float4 per row
#define NWARPS (LL / 32)

// Scratch (no device allocation allowed anywhere)
__device__ int g_perm[NB * LL];     // perm[n*LL + j] = source row for output row j (j < len_keep)
__device__ int g_lenkeep[NB];

// ---------------------------------------------------------------------------
// Kernel 1: per-sample selection + compaction + mask outputs.
// One block per sample, 512 threads (one per position).
//   keep[i] = i is among the len_keep smallest-noise positions with i < length-1
//   rank by counting with stable tie-break (matches jnp stable argsort)
//   compaction destination = exclusive position among kept (order-preserving)
// ---------------------------------------------------------------------------
__global__ void select_kernel(const float* __restrict__ noise,
                              const int* __restrict__ lengths,
                              float* __restrict__ out) {
    const int n    = blockIdx.x;
    const int i    = threadIdx.x;
    const int lane = i & 31;
    const int warp = i >> 5;

    __shared__ float ns[LL];
    __shared__ int   wsum[NWARPS];

    ns[i] = noise[n * LL + i];

    int length = lengths[n];
    length = max(16, min(LL, length));
    const int last     = length - 1;                     // candidates: i < last
    const int len_keep = (int)((float)length * 0.5f);    // f32 mul + trunc, matches ref
    __syncthreads();

    int keep = 0;
    if (i < last) {
        const float v = ns[i];
        int cnt = 0;
        #pragma unroll 4
        for (int j = 0; j < last; ++j) {
            const float w = ns[j];                        // smem broadcast — conflict-free
            cnt += (w < v) | ((w == v) & (j < i));        // stable-sort rank
        }
        keep = (cnt < len_keep);
    }

    // Inclusive scan of keep flags: warp scan, then cross-warp offsets.
    int ws = keep;
    #pragma unroll
    for (int off = 1; off < 32; off <<= 1) {
        int v = __shfl_up_sync(0xFFFFFFFFu, ws, off);
        if (lane >= off) ws += v;
    }
    if (lane == 31) wsum[warp] = ws;
    __syncthreads();
    if (warp == 0 && lane < NWARPS) {
        int v = wsum[lane];
        #pragma unroll
        for (int off = 1; off < NWARPS; off <<= 1) {
            int u = __shfl_up_sync(0xFFFFu, v, off);
            if (lane >= off) v += u;
        }
        wsum[lane] = v;   // inclusive warp totals
    }
    __syncthreads();
    const int incl = ws + (warp ? wsum[warp - 1] : 0);

    if (keep) g_perm[n * LL + (incl - 1)] = i;
    if (i == 0) g_lenkeep[n] = len_keep;

    // Mask outputs (packed after masked_x in d_out, return order)
    const long long MX = (long long)NB * LL * DD;
    const float m = (i < len_keep) ? 1.0f : 0.0f;
    out[MX + (long long)n * LL + i]            = m;           // masked_attention_mask
    out[MX + (long long)(NB + n) * LL + i]     = 1.0f - m;    // invert
    out[MX + (long long)(2 * NB + n) * LL + i] =
        (!keep && i < length) ? 1.0f : 0.0f;                  // removed_mask
}

// ---------------------------------------------------------------------------
// Kernel 2: row gather. One block per output row (n, j).
//   j <  len_keep : copy x[n, perm[j], :]   (mask == 1, no scaling needed)
//   j >= len_keep : zero                    (mask == 0)
// Pure HBM-bound: 110 MB store + ~28 MB gathered load.
// ---------------------------------------------------------------------------
__global__ void gather_kernel(const float* __restrict__ x,
                              float* __restrict__ out) {
    const int j = blockIdx.x;
    const int n = blockIdx.y;
    const int t = threadIdx.x;
    if (t >= NVEC) return;

    float4* __restrict__ orow =
        (float4*)(out + ((long long)(n * LL + j)) * DD);

    const int lk = g_lenkeep[n];
    if (j < lk) {
        const int src = g_perm[n * LL + j];
        const float4* __restrict__ xrow =
            (const float4*)(x + ((long long)(n * LL + src)) * DD);
        orow[t] = __ldg(&xrow[t]);
    } else {
        orow[t] = make_float4(0.f, 0.f, 0.f, 0.f);
    }
}

extern "C" void kernel_launch(void* const* d_in, const int* in_sizes, int n_in,
                              void* d_out, int out_size) {
    const float* x       = (const float*)d_in[0];   // [64, 512, 840] f32
    const float* noise   = (const float*)d_in[1];   // [64, 512] f32
    const int*   lengths = (const int*)d_in[2];     // [64] i32
    float* out = (float*)d_out;

    select_kernel<<<NB, LL>>>(noise, lengths, out);
    gather_kernel<<<dim3(LL, NB), 224>>>(x, out);   // 224 threads, 210 active (float4)
}

// round 7
// speedup vs baseline: 1.0824x; 1.0824x over previous
#include <cuda_runtime.h>
#include <cuda_bf16.h>

// Problem shape (fixed by reference setup_inputs)
#define NB 64
#define LL 512
#define DD 840
#define NVEC (DD / 4)     // 210 float4 per row
#define NWARPS (LL / 32)
#define NCH 4             // j-range chunks for the rank count
#define CH (LL / NCH)     // 128
#define ROWS_PER_BLK 16   // gather: warp-per-row, 16 warps/block

// Scratch (no device allocation allowed anywhere)
__device__ int g_cntp[NCH * NB * LL];  // partial rank counts per j-chunk
__device__ int g_perm[NB * LL];        // perm[n*LL+j] = source row for output row j
__device__ int g_lenkeep[NB];

// ---------------------------------------------------------------------------
// Kernel 1: partial rank count. Grid (NB, NCH), 512 threads.
// key = (float_bits << 9) | index  — noise in [0,1) is nonnegative so IEEE
// bits are order-monotonic; the packed index gives the stable tie-break.
// cnt_i^c = #{ j in chunk c, j < last : key_j < key_i }
// ---------------------------------------------------------------------------
__global__ void count_kernel(const float* __restrict__ noise,
                             const int* __restrict__ lengths) {
    const int n = blockIdx.x;
    const int c = blockIdx.y;
    const int i = threadIdx.x;

    __shared__ unsigned long long key[LL];

    int length = lengths[n];                   // hoisted: overlaps smem fill
    const unsigned int b = __float_as_uint(__ldg(&noise[n * LL + i]));
    key[i] = ((unsigned long long)b << 9) | (unsigned)i;

    length = max(16, min(LL, length));
    const int last = length - 1;               // candidates: j < last
    __syncthreads();

    const unsigned long long ki = key[i];
    const int j0 = c * CH;
    const int j1 = min(j0 + CH, last);
    int cnt = 0;
    #pragma unroll 4
    for (int j = j0; j < j1; ++j)
        cnt += (key[j] < ki);                  // smem broadcast, one u64 compare

    g_cntp[(c * NB + n) * LL + i] = cnt;
}

// ---------------------------------------------------------------------------
// Kernel 2: finalize. Grid NB, 512 threads.
// keep -> inclusive scan -> perm; writes the three mask outputs.
// ---------------------------------------------------------------------------
__global__ void finalize_kernel(const int* __restrict__ lengths,
                                float* __restrict__ out) {
    const int n    = blockIdx.x;
    const int i    = threadIdx.x;
    const int lane = i & 31;
    const int warp = i >> 5;

    __shared__ int wsum[NWARPS];

    int length = lengths[n];
    length = max(16, min(LL, length));
    const int last     = length - 1;
    const int len_keep = (int)((float)length * 0.5f);   // f32 mul + trunc, matches ref

    int cnt = 0;
    #pragma unroll
    for (int c = 0; c < NCH; ++c)
        cnt += g_cntp[(c * NB + n) * LL + i];

    const int keep = (i < last) && (cnt < len_keep);

    // Inclusive scan of keep flags: warp scan + cross-warp offsets
    int ws = keep;
    #pragma unroll
    for (int off = 1; off < 32; off <<= 1) {
        int v = __shfl_up_sync(0xFFFFFFFFu, ws, off);
        if (lane >= off) ws += v;
    }
    if (lane == 31) wsum[warp] = ws;
    __syncthreads();
    if (warp == 0 && lane < NWARPS) {
        int v = wsum[lane];
        #pragma unroll
        for (int off = 1; off < NWARPS; off <<= 1) {
            int u = __shfl_up_sync(0xFFFFu, v, off);
            if (lane >= off) v += u;
        }
        wsum[lane] = v;
    }
    __syncthreads();
    const int incl = ws + (warp ? wsum[warp - 1] : 0);

    if (keep) g_perm[n * LL + (incl - 1)] = i;
    if (i == 0) g_lenkeep[n] = len_keep;

    // Mask outputs (packed after masked_x in d_out, return order)
    const long long MX = (long long)NB * LL * DD;
    const float m = (i < len_keep) ? 1.0f : 0.0f;
    out[MX + (long long)n * LL + i]            = m;           // masked_attention_mask
    out[MX + (long long)(NB + n) * LL + i]     = 1.0f - m;    // invert
    out[MX + (long long)(2 * NB + n) * LL + i] =
        (!keep && i < length) ? 1.0f : 0.0f;                  // removed_mask
}

// ---------------------------------------------------------------------------
// Kernel 3: row gather, warp-per-row, 16 rows per block.
// Each thread batches 7 independent float4 loads (MLP=7) then 7 stores.
//   j <  len_keep : copy x[n, perm[j], :]
//   j >= len_keep : zero (mask == 0)
// ---------------------------------------------------------------------------
__global__ void gather_kernel(const float* __restrict__ x,
                              float* __restrict__ out) {
    const int lane = threadIdx.x & 31;
    const int warp = threadIdx.x >> 5;
    const int row  = blockIdx.x * ROWS_PER_BLK + warp;   // 0..NB*LL-1
    const int n = row >> 9;          // LL = 512
    const int j = row & (LL - 1);

    float4* __restrict__ orow = (float4*)(out + (long long)row * DD);
    const int lk = g_lenkeep[n];

    if (j < lk) {
        const int src = g_perm[n * LL + j];
        const float4* __restrict__ xrow =
            (const float4*)(x + ((long long)(n * LL + src)) * DD);
        float4 v[7];
        #pragma unroll
        for (int k = 0; k < 6; ++k) v[k] = __ldg(&xrow[lane + 32 * k]);
        if (lane < NVEC - 192) v[6] = __ldg(&xrow[lane + 192]);   // 210-192=18 lanes
        #pragma unroll
        for (int k = 0; k < 6; ++k) orow[lane + 32 * k] = v[k];
        if (lane < NVEC - 192) orow[lane + 192] = v[6];
    } else {
        const float4 z = make_float4(0.f, 0.f, 0.f, 0.f);
        #pragma unroll
        for (int k = 0; k < 6; ++k) orow[lane + 32 * k] = z;
        if (lane < NVEC - 192) orow[lane + 192] = z;
    }
}

extern "C" void kernel_launch(void* const* d_in, const int* in_sizes, int n_in,
                              void* d_out, int out_size) {
    const float* x       = (const float*)d_in[0];   // [64, 512, 840] f32
    const float* noise   = (const float*)d_in[1];   // [64, 512] f32
    const int*   lengths = (const int*)d_in[2];     // [64] i32
    float* out = (float*)d_out;

    count_kernel<<<dim3(NB, NCH), LL>>>(noise, lengths);
    finalize_kernel<<<NB, LL>>>(lengths, out);
    gather_kernel<<<(NB * LL) / ROWS_PER_BLK, ROWS_PER_BLK * 32>>>(x, out);
}